// round 2
// baseline (speedup 1.0000x reference)
#include <cuda_runtime.h>

#define DX 256
#define DY 256
#define DZ 32
#define VOL  (DX * DY * DZ)   // 2,097,152 floats
#define VOL4 (VOL / 4)        // 524,288 float4

// Ping-pong scratch (8 MB), device global = allowed scratch mechanism.
__device__ float4 g_scratch4[VOL4];

__device__ __forceinline__ float4 f4z() { return make_float4(0.f, 0.f, 0.f, 0.f); }

// Shift a z-row float4 by +1 in z (value needed at z+1). The 8 lanes of a
// z-group (lane&~7 .. lane|7) hold one full z=0..31 row. z=32 is zero-pad.
__device__ __forceinline__ float4 shiftp(float4 v, int lane) {
    float nxt = __shfl_down_sync(0xffffffffu, v.x, 1);
    if ((lane & 7) == 7) nxt = 0.f;
    return make_float4(v.y, v.z, v.w, nxt);
}
// Shift by -1 in z (value needed at z-1). z=-1 is zero-pad.
__device__ __forceinline__ float4 shiftm(float4 v, int lane) {
    float prv = __shfl_up_sync(0xffffffffu, v.w, 1);
    if ((lane & 7) == 0) prv = 0.f;
    return make_float4(prv, v.x, v.y, v.z);
}

__device__ __forceinline__ void acc(float4& aa, float4& gg, float4& ww,
                                    const float4 g, const float4 b) {
    aa.x += fabsf(g.x); aa.y += fabsf(g.y); aa.z += fabsf(g.z); aa.w += fabsf(g.w);
    gg.x += g.x;        gg.y += g.y;        gg.z += g.z;        gg.w += g.w;
    ww.x = fmaf(g.x, b.x, ww.x); ww.y = fmaf(g.y, b.y, ww.y);
    ww.z = fmaf(g.z, b.z, ww.z); ww.w = fmaf(g.w, b.w, ww.w);
}

// Neighbor tables (row, col), matching the reference ZeroPad2d shift set:
// DIR=0: row->x, col->y (channels 0..7,  per-z plane)
// DIR=1: row->x, col->z (channels 8..15, per-y plane)
// DIR=2: row->y, col->z (channels 16..23, per-x plane)
template <int DIR>
__global__ __launch_bounds__(256) void prop_step(
    const float4* __restrict__ G,   // guidance [24][VOL4]
    const float4* __restrict__ S,   // src [VOL4]
    float4* __restrict__ D)         // dst [VOL4]
{
    const int t    = blockIdx.x * 256 + threadIdx.x;
    const int lane = threadIdx.x & 31;
    const int zq   = t & 7;            // which float4 within the z-row
    const int y    = (t >> 3) & 255;
    const int x    = t >> 11;

    constexpr int DR[8] = { 1, 1, 1, 0, 0, -1, -1, -1 };
    constexpr int DC[8] = { 1, 0, -1, 1, -1, 1, 0, -1 };

    float4 aa = f4z(), gg = f4z(), ww = f4z();
    const float4 bc = S[t];

    if (DIR == 0) {
        // All shifts in (x,y): every load is an aligned float4.
#pragma unroll
        for (int k = 0; k < 8; ++k) {
            const int nx = x + DR[k], ny = y + DC[k];
            const bool ok = ((unsigned)nx < DX) & ((unsigned)ny < DY);
            float4 g = f4z(), b = f4z();
            if (ok) {
                const int ni = (nx * DY + ny) * 8 + zq;
                g = G[k * VOL4 + ni];
                b = S[ni];
            }
            acc(aa, gg, ww, g, b);
        }
    } else {
        // col shift is along z: aligned loads + in-register shuffle shifts.
        // Preload the 3 blur rows (row offset -1,0,+1) and their z-shifts.
        float4 br0[3], brp[3], brm[3];
#pragma unroll
        for (int r = 0; r < 3; ++r) {
            const int d  = r - 1;
            const int rx = (DIR == 1) ? x + d : x;
            const int ry = (DIR == 1) ? y     : y + d;
            const bool ok = (DIR == 1) ? ((unsigned)rx < DX) : ((unsigned)ry < DY);
            float4 v = f4z();
            if (ok) v = S[(rx * DY + ry) * 8 + zq];
            br0[r] = v;
            brp[r] = shiftp(v, lane);
            brm[r] = shiftm(v, lane);
        }
#pragma unroll
        for (int k = 0; k < 8; ++k) {
            const int d  = DR[k];
            const int rx = (DIR == 1) ? x + d : x;
            const int ry = (DIR == 1) ? y     : y + d;
            const bool ok = (DIR == 1) ? ((unsigned)rx < DX) : ((unsigned)ry < DY);
            float4 g = f4z();
            if (ok) g = G[(DIR * 8 + k) * VOL4 + (rx * DY + ry) * 8 + zq];
            if (DC[k] == 1)       g = shiftp(g, lane);
            else if (DC[k] == -1) g = shiftm(g, lane);
            const int ri = DR[k] + 1;
            const float4 b = (DC[k] == 1) ? brp[ri] : ((DC[k] == -1) ? brm[ri] : br0[ri]);
            acc(aa, gg, ww, g, b);
        }
    }

    // out = (1 - gg/aa)*bc + ww/aa = bc + (ww - gg*bc)/aa
    float4 r;
    r.x = fmaf(fmaf(-gg.x, bc.x, ww.x), __fdividef(1.f, aa.x), bc.x);
    r.y = fmaf(fmaf(-gg.y, bc.y, ww.y), __fdividef(1.f, aa.y), bc.y);
    r.z = fmaf(fmaf(-gg.z, bc.z, ww.z), __fdividef(1.f, aa.z), bc.z);
    r.w = fmaf(fmaf(-gg.w, bc.w, ww.w), __fdividef(1.f, aa.w), bc.w);
    D[t] = r;
}

extern "C" void kernel_launch(void* const* d_in, const int* in_sizes, int n_in,
                              void* d_out, int out_size)
{
    const float4* G    = (const float4*)d_in[0];  // guidance [24,256,256,32]
    const float4* blur = (const float4*)d_in[1];  // blur [1,256,256,32]
    float4* out = (float4*)d_out;

    void* sp = nullptr;
    cudaGetSymbolAddress(&sp, g_scratch4);
    float4* scr = (float4*)sp;

    const int grid = VOL4 / 256;   // 2048 blocks

    // 9 steps (dir 0,1,2 × 3). Ping-pong so the 9th write lands in d_out:
    // targets: out, scr, out, scr, out, scr, out, scr, out.
    const float4* src = blur;
    float4* bufs[2] = { out, scr };
    int w = 0;

    for (int it = 0; it < 3; ++it) {
        prop_step<0><<<grid, 256>>>(G, src, bufs[w]);
        src = bufs[w]; w ^= 1;
        prop_step<1><<<grid, 256>>>(G, src, bufs[w]);
        src = bufs[w]; w ^= 1;
        prop_step<2><<<grid, 256>>>(G, src, bufs[w]);
        src = bufs[w]; w ^= 1;
    }
}

// round 3
// speedup vs baseline: 1.0446x; 1.0446x over previous
#include <cuda_runtime.h>

#define DX 256
#define DY 256
#define DZ 32
#define VOL (DX * DY * DZ)   // 2,097,152

// Precomputed int16 weights, interleaved [dir][voxel][8] (16B/voxel) = 96 MB,
// plus 8 MB ping-pong scratch. Device globals = the allowed scratch mechanism.
__device__ uint4 g_weights[3][VOL];
__device__ float g_scratch[VOL];

// Neighbor shift tables (row, col) from the reference ZeroPad2d set.
// DIR=0: row->x, col->y (channels 0..7);  DIR=1: row->x, col->z (8..15);
// DIR=2: row->y, col->z (16..23).
__device__ __constant__ const int c_dr[8] = { 1, 1, 1, 0, 0, -1, -1, -1 };
__device__ __constant__ const int c_dc[8] = { 1, 0, -1, 1, -1, 1, 0, -1 };

// ---------------------------------------------------------------------------
// Pass 1: gather 8 guidance values at the neighbor positions, abs-sum
// normalize, quantize to int16 (x32767), pack 8 per voxel (one 16B store).
// Out-of-range neighbors quantize to exactly 0.
// ---------------------------------------------------------------------------
template <int DIR>
__global__ __launch_bounds__(256) void make_weights(
    const float* __restrict__ G, uint4* __restrict__ W)
{
    const int t = blockIdx.x * 256 + threadIdx.x;
    const int z = t & 31, y = (t >> 5) & 255, x = t >> 13;

    float g[8];
    float asum = 0.f;
#pragma unroll
    for (int k = 0; k < 8; ++k) {
        const int dr = c_dr[k], dc = c_dc[k];
        int nx, ny, nz; bool ok;
        if (DIR == 0)      { nx = x + dr; ny = y + dc; nz = z;
                             ok = ((unsigned)nx < DX) & ((unsigned)ny < DY); }
        else if (DIR == 1) { nx = x + dr; ny = y;      nz = z + dc;
                             ok = ((unsigned)nx < DX) & ((unsigned)nz < DZ); }
        else               { nx = x;      ny = y + dr; nz = z + dc;
                             ok = ((unsigned)ny < DY) & ((unsigned)nz < DZ); }
        float v = 0.f;
        if (ok) v = __ldg(&G[(DIR * 8 + k) * VOL + (nx * DY + ny) * DZ + nz]);
        g[k] = v;
        asum += fabsf(v);
    }

    const float s = 32767.f / asum;
    int q[8];
#pragma unroll
    for (int k = 0; k < 8; ++k) q[k] = __float2int_rn(g[k] * s);

    uint4 w;
    w.x = (q[0] & 0xffff) | (q[1] << 16);
    w.y = (q[2] & 0xffff) | (q[3] << 16);
    w.z = (q[4] & 0xffff) | (q[5] << 16);
    w.w = (q[6] & 0xffff) | (q[7] << 16);
    W[t] = w;
}

// ---------------------------------------------------------------------------
// Pass 2 (x9): one 16B weight load + 9 blur loads + 1 store per voxel.
// out = bc + (sum_k w_k*b_k - (sum_k w_k)*bc) / 32767
// Invalid neighbors have w_k == 0, so we just clamp the address to center.
// ---------------------------------------------------------------------------
template <int DIR>
__global__ __launch_bounds__(256) void prop_step(
    const uint4* __restrict__ W,
    const float* __restrict__ S,
    float* __restrict__ D)
{
    const int t = blockIdx.x * 256 + threadIdx.x;
    const int z = t & 31, y = (t >> 5) & 255, x = t >> 13;

    const uint4 w = W[t];
    const float bc = S[t];

    float wf[8];
    wf[0] = (float)(short)(w.x & 0xffff); wf[1] = (float)(short)(w.x >> 16);
    wf[2] = (float)(short)(w.y & 0xffff); wf[3] = (float)(short)(w.y >> 16);
    wf[4] = (float)(short)(w.z & 0xffff); wf[5] = (float)(short)(w.z >> 16);
    wf[6] = (float)(short)(w.w & 0xffff); wf[7] = (float)(short)(w.w >> 16);

    float acc = 0.f, gs = 0.f;
#pragma unroll
    for (int k = 0; k < 8; ++k) {
        const int dr = c_dr[k], dc = c_dc[k];
        int delta; bool ok;
        if (DIR == 0)      { ok = ((unsigned)(x + dr) < DX) & ((unsigned)(y + dc) < DY);
                             delta = dr * (DY * DZ) + dc * DZ; }
        else if (DIR == 1) { ok = ((unsigned)(x + dr) < DX) & ((unsigned)(z + dc) < DZ);
                             delta = dr * (DY * DZ) + dc; }
        else               { ok = ((unsigned)(y + dr) < DY) & ((unsigned)(z + dc) < DZ);
                             delta = dr * DZ + dc; }
        const float b = __ldg(&S[ok ? t + delta : t]);
        acc = fmaf(wf[k], b, acc);
        gs += wf[k];
    }

    D[t] = fmaf(fmaf(-gs, bc, acc), 1.f / 32767.f, bc);
}

extern "C" void kernel_launch(void* const* d_in, const int* in_sizes, int n_in,
                              void* d_out, int out_size)
{
    const float* G    = (const float*)d_in[0];  // guidance [24,256,256,32]
    const float* blur = (const float*)d_in[1];  // blur [1,256,256,32]
    float* out = (float*)d_out;

    void* wp = nullptr;  cudaGetSymbolAddress(&wp, g_weights);
    void* sp = nullptr;  cudaGetSymbolAddress(&sp, g_scratch);
    uint4* W   = (uint4*)wp;
    float* scr = (float*)sp;

    const int grid = VOL / 256;   // 8192 blocks

    // Pass 1: build weights for the 3 directions (guidance read exactly once).
    make_weights<0><<<grid, 256>>>(G, W + 0 * VOL);
    make_weights<1><<<grid, 256>>>(G, W + 1 * VOL);
    make_weights<2><<<grid, 256>>>(G, W + 2 * VOL);

    // Pass 2: 9 propagation steps (dir 0,1,2 x 3), ping-pong so the 9th
    // write lands in d_out: targets out,scr,out,scr,out,scr,out,scr,out.
    const float* src = blur;
    float* bufs[2] = { out, scr };
    int wsel = 0;

    for (int it = 0; it < 3; ++it) {
        prop_step<0><<<grid, 256>>>(W + 0 * VOL, src, bufs[wsel]);
        src = bufs[wsel]; wsel ^= 1;
        prop_step<1><<<grid, 256>>>(W + 1 * VOL, src, bufs[wsel]);
        src = bufs[wsel]; wsel ^= 1;
        prop_step<2><<<grid, 256>>>(W + 2 * VOL, src, bufs[wsel]);
        src = bufs[wsel]; wsel ^= 1;
    }
}

// round 5
// speedup vs baseline: 1.0609x; 1.0156x over previous
#include <cuda_runtime.h>

#define DX 256
#define DY 256
#define DZ 32
#define VOL  (DX * DY * DZ)   // 2,097,152
#define HVOL (VOL / 2)

// Precomputed int16 weights, interleaved [dir][voxel][8] (16B/voxel) = 96 MB,
// plus 8 MB ping-pong scratch. Device globals = the allowed scratch mechanism.
__device__ uint4 g_weights[3][VOL];
__device__ float g_scratch[VOL];

// Neighbor shift tables (row, col) from the reference ZeroPad2d set.
// DIR=0: row->x, col->y (channels 0..7);  DIR=1: row->x, col->z (8..15);
// DIR=2: row->y, col->z (16..23).
__device__ __constant__ const int c_dr[8] = { 1, 1, 1, 0, 0, -1, -1, -1 };
__device__ __constant__ const int c_dc[8] = { 1, 0, -1, 1, -1, 1, 0, -1 };

__device__ __forceinline__ float ldcs(const float* p) {
    float v;
    asm volatile("ld.global.cs.f32 %0, [%1];" : "=f"(v) : "l"(p));
    return v;
}

// ---------------------------------------------------------------------------
// Pass 1: gather 8 guidance values at neighbor positions, abs-sum normalize,
// quantize to int16 (x32767), pack 8 per voxel. 2 voxels/thread for MLP.
// Guidance is single-use -> .cs streaming loads (don't evict weights from L2).
// ---------------------------------------------------------------------------
template <int DIR>
__global__ __launch_bounds__(256) void make_weights(
    const float* __restrict__ G, uint4* __restrict__ W)
{
    const int t0 = blockIdx.x * 256 + threadIdx.x;

#pragma unroll
    for (int v = 0; v < 2; ++v) {
        const int t = t0 + v * HVOL;
        const int z = t & 31, y = (t >> 5) & 255, x = t >> 13;

        float g[8];
        float asum = 0.f;
#pragma unroll
        for (int k = 0; k < 8; ++k) {
            const int dr = c_dr[k], dc = c_dc[k];
            int nx, ny, nz; bool ok;
            if (DIR == 0)      { nx = x + dr; ny = y + dc; nz = z;
                                 ok = ((unsigned)nx < DX) & ((unsigned)ny < DY); }
            else if (DIR == 1) { nx = x + dr; ny = y;      nz = z + dc;
                                 ok = ((unsigned)nx < DX) & ((unsigned)nz < DZ); }
            else               { nx = x;      ny = y + dr; nz = z + dc;
                                 ok = ((unsigned)ny < DY) & ((unsigned)nz < DZ); }
            float gv = 0.f;
            if (ok) gv = ldcs(&G[(DIR * 8 + k) * VOL + (nx * DY + ny) * DZ + nz]);
            g[k] = gv;
            asum += fabsf(gv);
        }

        const float s = 32767.f / asum;
        int q[8];
#pragma unroll
        for (int k = 0; k < 8; ++k) q[k] = __float2int_rn(g[k] * s);

        uint4 w;
        w.x = (q[0] & 0xffff) | (q[1] << 16);
        w.y = (q[2] & 0xffff) | (q[3] << 16);
        w.z = (q[4] & 0xffff) | (q[5] << 16);
        w.w = (q[6] & 0xffff) | (q[7] << 16);
        W[t] = w;
    }
}

// ---------------------------------------------------------------------------
// Pass 2 (x9): per voxel: 1x16B weight load + 9 blur loads + 1 store.
// out = bc + (sum_k w_k*b_k - (sum_k w_k)*bc) / 32767.
// Invalid neighbors have w_k == 0, so just clamp the address to center.
// 2 voxels/thread (t, t+HVOL): ~20 independent loads in flight per thread.
// ---------------------------------------------------------------------------
template <int DIR>
__global__ __launch_bounds__(256) void prop_step(
    const uint4* __restrict__ W,
    const float* __restrict__ S,
    float* __restrict__ D)
{
    const int t0 = blockIdx.x * 256 + threadIdx.x;

    uint4  w[2];
    float  bc[2];
    float  b[2][8];

    // Issue all loads for both voxels first (maximize outstanding loads).
#pragma unroll
    for (int v = 0; v < 2; ++v) {
        const int t = t0 + v * HVOL;
        const int z = t & 31, y = (t >> 5) & 255, x = t >> 13;
        w[v]  = W[t];
        bc[v] = __ldg(&S[t]);
#pragma unroll
        for (int k = 0; k < 8; ++k) {
            const int dr = c_dr[k], dc = c_dc[k];
            int delta; bool ok;
            if (DIR == 0)      { ok = ((unsigned)(x + dr) < DX) & ((unsigned)(y + dc) < DY);
                                 delta = dr * (DY * DZ) + dc * DZ; }
            else if (DIR == 1) { ok = ((unsigned)(x + dr) < DX) & ((unsigned)(z + dc) < DZ);
                                 delta = dr * (DY * DZ) + dc; }
            else               { ok = ((unsigned)(y + dr) < DY) & ((unsigned)(z + dc) < DZ);
                                 delta = dr * DZ + dc; }
            b[v][k] = __ldg(&S[ok ? t + delta : t]);
        }
    }

#pragma unroll
    for (int v = 0; v < 2; ++v) {
        float wf[8];
        wf[0] = (float)(short)(w[v].x & 0xffff); wf[1] = (float)(short)(w[v].x >> 16);
        wf[2] = (float)(short)(w[v].y & 0xffff); wf[3] = (float)(short)(w[v].y >> 16);
        wf[4] = (float)(short)(w[v].z & 0xffff); wf[5] = (float)(short)(w[v].z >> 16);
        wf[6] = (float)(short)(w[v].w & 0xffff); wf[7] = (float)(short)(w[v].w >> 16);

        float acc = 0.f, gs = 0.f;
#pragma unroll
        for (int k = 0; k < 8; ++k) {
            acc = fmaf(wf[k], b[v][k], acc);
            gs += wf[k];
        }
        D[t0 + v * HVOL] = fmaf(fmaf(-gs, bc[v], acc), 1.f / 32767.f, bc[v]);
    }
}

extern "C" void kernel_launch(void* const* d_in, const int* in_sizes, int n_in,
                              void* d_out, int out_size)
{
    const float* G    = (const float*)d_in[0];  // guidance [24,256,256,32]
    const float* blur = (const float*)d_in[1];  // blur [1,256,256,32]
    float* out = (float*)d_out;

    void* wp = nullptr;  cudaGetSymbolAddress(&wp, g_weights);
    void* sp = nullptr;  cudaGetSymbolAddress(&sp, g_scratch);
    uint4* W   = (uint4*)wp;
    float* scr = (float*)sp;

    const int grid = HVOL / 256;   // 4096 blocks, 2 voxels/thread

    // Pass 1: build weights for the 3 directions (guidance read exactly once).
    make_weights<0><<<grid, 256>>>(G, W + 0 * VOL);
    make_weights<1><<<grid, 256>>>(G, W + 1 * VOL);
    make_weights<2><<<grid, 256>>>(G, W + 2 * VOL);

    // Pass 2: 9 propagation steps (dir 0,1,2 x 3), ping-pong so the 9th
    // write lands in d_out: targets out,scr,out,scr,out,scr,out,scr,out.
    const float* src = blur;
    float* bufs[2] = { out, scr };
    int wsel = 0;

    for (int it = 0; it < 3; ++it) {
        prop_step<0><<<grid, 256>>>(W + 0 * VOL, src, bufs[wsel]);
        src = bufs[wsel]; wsel ^= 1;
        prop_step<1><<<grid, 256>>>(W + 1 * VOL, src, bufs[wsel]);
        src = bufs[wsel]; wsel ^= 1;
        prop_step<2><<<grid, 256>>>(W + 2 * VOL, src, bufs[wsel]);
        src = bufs[wsel]; wsel ^= 1;
    }
}

// round 8
// speedup vs baseline: 1.0805x; 1.0185x over previous
#include <cuda_runtime.h>

#define DX 256
#define DY 256
#define DZ 32
#define VOL (DX * DY * DZ)   // 2,097,152

// Precomputed int16 weights, interleaved [dir][voxel][8] (16B/voxel) = 96 MB,
// plus 8 MB ping-pong scratch. Device globals = the allowed scratch mechanism.
__device__ uint4 g_weights[3][VOL];
__device__ float g_scratch[VOL];

// Neighbor shift tables (row, col) from the reference ZeroPad2d set.
// DIR=0: row->x, col->y (channels 0..7);  DIR=1: row->x, col->z (8..15);
// DIR=2: row->y, col->z (16..23).
__device__ __constant__ const int c_dr[8] = { 1, 1, 1, 0, 0, -1, -1, -1 };
__device__ __constant__ const int c_dc[8] = { 1, 0, -1, 1, -1, 1, 0, -1 };

// Single-use guidance: stream through, evict first.
__device__ __forceinline__ float ldcs(const float* p) {
    float v;
    asm volatile("ld.global.cs.f32 %0, [%1];" : "=f"(v) : "l"(p));
    return v;
}
// 256-bit sticky L2 accesses (the only width ptxas allows evict_last on).
__device__ __forceinline__ void ldg256_sticky(const uint4* p, uint4& a, uint4& b) {
    asm volatile("ld.global.L2::evict_last.v8.b32 {%0,%1,%2,%3,%4,%5,%6,%7}, [%8];"
                 : "=r"(a.x), "=r"(a.y), "=r"(a.z), "=r"(a.w),
                   "=r"(b.x), "=r"(b.y), "=r"(b.z), "=r"(b.w)
                 : "l"(p));
}
__device__ __forceinline__ void stg256_sticky(uint4* p, uint4 a, uint4 b) {
    asm volatile("st.global.L2::evict_last.v8.b32 [%0], {%1,%2,%3,%4,%5,%6,%7,%8};"
                 :: "l"(p),
                    "r"(a.x), "r"(a.y), "r"(a.z), "r"(a.w),
                    "r"(b.x), "r"(b.y), "r"(b.z), "r"(b.w)
                 : "memory");
}

// ---------------------------------------------------------------------------
// Pass 1: gather 8 guidance values at neighbor positions, abs-sum normalize,
// quantize to int16 (x32767). Two adjacent voxels per thread -> one 256-bit
// sticky store (weight slabs enter L2 evict-last).
// ---------------------------------------------------------------------------
template <int DIR>
__global__ __launch_bounds__(256) void make_weights(
    const float* __restrict__ G, uint4* __restrict__ W)
{
    const int t = (blockIdx.x * 256 + threadIdx.x) * 2;
    const int z0 = t & 31, y = (t >> 5) & 255, x = t >> 13;

    uint4 wp[2];
#pragma unroll
    for (int v = 0; v < 2; ++v) {
        const int z = z0 + v;
        float g[8];
        float asum = 0.f;
#pragma unroll
        for (int k = 0; k < 8; ++k) {
            const int dr = c_dr[k], dc = c_dc[k];
            int nx, ny, nz; bool ok;
            if (DIR == 0)      { nx = x + dr; ny = y + dc; nz = z;
                                 ok = ((unsigned)nx < DX) & ((unsigned)ny < DY); }
            else if (DIR == 1) { nx = x + dr; ny = y;      nz = z + dc;
                                 ok = ((unsigned)nx < DX) & ((unsigned)nz < DZ); }
            else               { nx = x;      ny = y + dr; nz = z + dc;
                                 ok = ((unsigned)ny < DY) & ((unsigned)nz < DZ); }
            float gv = 0.f;
            if (ok) gv = ldcs(&G[(DIR * 8 + k) * VOL + (nx * DY + ny) * DZ + nz]);
            g[k] = gv;
            asum += fabsf(gv);
        }

        const float s = 32767.f / asum;
        int q[8];
#pragma unroll
        for (int k = 0; k < 8; ++k) q[k] = __float2int_rn(g[k] * s);

        wp[v].x = (q[0] & 0xffff) | (q[1] << 16);
        wp[v].y = (q[2] & 0xffff) | (q[3] << 16);
        wp[v].z = (q[4] & 0xffff) | (q[5] << 16);
        wp[v].w = (q[6] & 0xffff) | (q[7] << 16);
    }
    stg256_sticky(&W[t], wp[0], wp[1]);
}

// ---------------------------------------------------------------------------
// Pass 2 (x9): two adjacent voxels per thread.
//   1 x 256-bit sticky weight load, float2 center, DIR0: 8 float2 neighbor
//   loads, DIR1/2: 16 scalar neighbor loads, 1 float2 store.
// out = bc + (sum_k w_k*b_k - (sum_k w_k)*bc) / 32767.
// Invalid neighbors have w_k == 0; address is clamped to center (value unused).
// ---------------------------------------------------------------------------
template <int DIR>
__global__ __launch_bounds__(256) void prop_step(
    const uint4* __restrict__ W,
    const float* __restrict__ S,
    float* __restrict__ D)
{
    const int t = (blockIdx.x * 256 + threadIdx.x) * 2;
    const int z = t & 31, y = (t >> 5) & 255, x = t >> 13;

    uint4 w0, w1;
    ldg256_sticky(&W[t], w0, w1);
    const float2 bc = *reinterpret_cast<const float2*>(S + t);

    float b0[8], b1[8];
    if (DIR == 0) {
        // Shifts in (x,y) only: both voxels share delta; float2 loads stay aligned.
#pragma unroll
        for (int k = 0; k < 8; ++k) {
            const int dr = c_dr[k], dc = c_dc[k];
            const bool ok = ((unsigned)(x + dr) < DX) & ((unsigned)(y + dc) < DY);
            const int delta = dr * (DY * DZ) + dc * DZ;
            const float2 bb = *reinterpret_cast<const float2*>(S + (ok ? t + delta : t));
            b0[k] = bb.x; b1[k] = bb.y;
        }
    } else {
#pragma unroll
        for (int k = 0; k < 8; ++k) {
            const int dr = c_dr[k], dc = c_dc[k];
            const int  row = (DIR == 1) ? dr * (DY * DZ) : dr * DZ;
            const bool rok = (DIR == 1) ? ((unsigned)(x + dr) < DX)
                                        : ((unsigned)(y + dr) < DY);
            const bool ok0 = rok & ((unsigned)(z + dc)     < DZ);
            const bool ok1 = rok & ((unsigned)(z + 1 + dc) < DZ);
            b0[k] = __ldg(&S[ok0 ? t + row + dc     : t]);
            b1[k] = __ldg(&S[ok1 ? t + 1 + row + dc : t]);
        }
    }

    float2 r;
    {
        float wf[8];
        wf[0] = (float)(short)(w0.x & 0xffff); wf[1] = (float)(short)(w0.x >> 16);
        wf[2] = (float)(short)(w0.y & 0xffff); wf[3] = (float)(short)(w0.y >> 16);
        wf[4] = (float)(short)(w0.z & 0xffff); wf[5] = (float)(short)(w0.z >> 16);
        wf[6] = (float)(short)(w0.w & 0xffff); wf[7] = (float)(short)(w0.w >> 16);
        float acc = 0.f, gs = 0.f;
#pragma unroll
        for (int k = 0; k < 8; ++k) { acc = fmaf(wf[k], b0[k], acc); gs += wf[k]; }
        r.x = fmaf(fmaf(-gs, bc.x, acc), 1.f / 32767.f, bc.x);
    }
    {
        float wf[8];
        wf[0] = (float)(short)(w1.x & 0xffff); wf[1] = (float)(short)(w1.x >> 16);
        wf[2] = (float)(short)(w1.y & 0xffff); wf[3] = (float)(short)(w1.y >> 16);
        wf[4] = (float)(short)(w1.z & 0xffff); wf[5] = (float)(short)(w1.z >> 16);
        wf[6] = (float)(short)(w1.w & 0xffff); wf[7] = (float)(short)(w1.w >> 16);
        float acc = 0.f, gs = 0.f;
#pragma unroll
        for (int k = 0; k < 8; ++k) { acc = fmaf(wf[k], b1[k], acc); gs += wf[k]; }
        r.y = fmaf(fmaf(-gs, bc.y, acc), 1.f / 32767.f, bc.y);
    }
    *reinterpret_cast<float2*>(D + t) = r;
}

extern "C" void kernel_launch(void* const* d_in, const int* in_sizes, int n_in,
                              void* d_out, int out_size)
{
    const float* G    = (const float*)d_in[0];  // guidance [24,256,256,32]
    const float* blur = (const float*)d_in[1];  // blur [1,256,256,32]
    float* out = (float*)d_out;

    void* wp = nullptr;  cudaGetSymbolAddress(&wp, g_weights);
    void* sp = nullptr;  cudaGetSymbolAddress(&sp, g_scratch);
    uint4* W   = (uint4*)wp;
    float* scr = (float*)sp;

    const int grid = (VOL / 2) / 256;   // 4096 blocks, 2 voxels/thread

    // Pass 1: build weights for the 3 directions (guidance read exactly once).
    make_weights<0><<<grid, 256>>>(G, W + 0 * VOL);
    make_weights<1><<<grid, 256>>>(G, W + 1 * VOL);
    make_weights<2><<<grid, 256>>>(G, W + 2 * VOL);

    // Pass 2: 9 propagation steps (dir 0,1,2 x 3), ping-pong so the 9th
    // write lands in d_out: targets out,scr,out,scr,out,scr,out,scr,out.
    const float* src = blur;
    float* bufs[2] = { out, scr };
    int wsel = 0;

    for (int it = 0; it < 3; ++it) {
        prop_step<0><<<grid, 256>>>(W + 0 * VOL, src, bufs[wsel]);
        src = bufs[wsel]; wsel ^= 1;
        prop_step<1><<<grid, 256>>>(W + 1 * VOL, src, bufs[wsel]);
        src = bufs[wsel]; wsel ^= 1;
        prop_step<2><<<grid, 256>>>(W + 2 * VOL, src, bufs[wsel]);
        src = bufs[wsel]; wsel ^= 1;
    }
}